// round 15
// baseline (speedup 1.0000x reference)
#include <cuda_runtime.h>
#include <cstdint>
#include <math_constants.h>

// Sparsemax along last dim (d = 1024), one warp per row, row in registers.
// PERSISTENT grid-stride form of the best kernel (R13): grid sized to one
// full wave (9 blocks/SM x 148 SMs); each warp loops over ~6 rows, removing
// ~5 wave transitions and tail-wave imbalance. Per-row compute unchanged:
// Michelot fixed-point from tau0 = max(z)-1 (valid: tau* >= max-1), actives
// binned into 3+3 regs/lane via two independent 16-deep chains, iterations
// via single-instruction integer redux.sync on 2^21 fixed-point sums.
// Rare overflow -> full-register float-shuffle fallback.
// No smem, no block barriers; loop bounds are warp-uniform.

constexpr int D   = 1024;
constexpr int WPB = 4;               // warps per block
constexpr int TPB = WPB * 32;        // 128 threads
constexpr int GRID_PERSIST = 148 * 9;  // one full wave at 55 regs/128thr

#define FPSCALE     2097152.0f        // 2^21
#define FPSCALE_INV 4.76837158203125e-7f

// Order-preserving float<->int mapping (valid for non-NaN inputs).
__device__ __forceinline__ int f2i_mono(float f) {
    int i = __float_as_int(f);
    return i >= 0 ? i : i ^ 0x7fffffff;
}
__device__ __forceinline__ float i2f_mono(int i) {
    return __int_as_float(i >= 0 ? i : i ^ 0x7fffffff);
}

__device__ __forceinline__ float warp_sum(float x) {
#pragma unroll
    for (int o = 16; o > 0; o >>= 1)
        x += __shfl_xor_sync(0xffffffffu, x, o);
    return x;
}

__global__ void __launch_bounds__(TPB)
sparsemax_kernel(const float* __restrict__ z, float* __restrict__ p, int rows) {
    const int wl    = threadIdx.x >> 5;
    const int lane  = threadIdx.x & 31;
    const int wstep = gridDim.x * WPB;           // total warps in grid

#pragma unroll 1
    for (int row = blockIdx.x * WPB + wl; row < rows; row += wstep) {
        const float* zr = z + (size_t)row * D + lane * 4;
        float*       pr = p + (size_t)row * D + lane * 4;

        // ---- load row: 8 x float4 per lane, coalesced, streaming ----
        float v[32];
#pragma unroll
        for (int j = 0; j < 8; j++) {
            float4 t = __ldcs(reinterpret_cast<const float4*>(zr + j * 128));
            v[4 * j + 0] = t.x;
            v[4 * j + 1] = t.y;
            v[4 * j + 2] = t.z;
            v[4 * j + 3] = t.w;
        }

        // ---- row max: register tree (ILP) + single-instruction int redux ----
        float m = v[0];
#pragma unroll
        for (int i = 1; i < 32; i++) m = fmaxf(m, v[i]);
        m = i2f_mono(__reduce_max_sync(0xffffffffu, f2i_mono(m)));

        float tau = m - 1.0f;

        // ---- bin actives {z > tau0}: two independent 16-deep chains ----
        float x0 = -CUDART_INF_F, x1 = -CUDART_INF_F, x2 = -CUDART_INF_F;
        float x3 = -CUDART_INF_F, x4 = -CUDART_INF_F, x5 = -CUDART_INF_F;
        int lc0 = 0, lc1 = 0;
#pragma unroll
        for (int i = 0; i < 16; i++) {
            if (v[i] > tau) {
                if (lc0 == 0)      x0 = v[i];
                else if (lc0 == 1) x1 = v[i];
                else if (lc0 == 2) x2 = v[i];
                lc0++;
            }
        }
#pragma unroll
        for (int i = 16; i < 32; i++) {
            if (v[i] > tau) {
                if (lc1 == 0)      x3 = v[i];
                else if (lc1 == 1) x4 = v[i];
                else if (lc1 == 2) x5 = v[i];
                lc1++;
            }
        }
        const bool overflow =
            __ballot_sync(0xffffffffu, (lc0 > 3) || (lc1 > 3)) != 0u;

        // ---- Michelot fixed-point iterations ----
        if (!overflow) {
            // common case: all actives in x0..x5 across the warp
#pragma unroll 1
            for (int it = 0; it < 40; it++) {
                bool a0 = x0 > tau, a1 = x1 > tau, a2 = x2 > tau;
                bool a3 = x3 > tau, a4 = x4 > tau, a5 = x5 > tau;
                float ls = ((a0 ? x0 : 0.0f) + (a1 ? x1 : 0.0f))
                         + ((a2 ? x2 : 0.0f) + (a3 ? x3 : 0.0f))
                         + ((a4 ? x4 : 0.0f) + (a5 ? x5 : 0.0f));
                int lk = (int)a0 + (int)a1 + (int)a2
                       + (int)a3 + (int)a4 + (int)a5;
                int S = __reduce_add_sync(0xffffffffu,
                                          __float2int_rn(ls * FPSCALE));
                int K = __reduce_add_sync(0xffffffffu, lk);  // K >= 1 always
                float nt = ((float)S * FPSCALE_INV - 1.0f) / (float)K;
                if (nt == tau) break;  // fixed point = exact threshold
                tau = nt;
            }
        } else {
            // rare fallback: full register row, float shuffle reductions
#pragma unroll 1
            for (int it = 0; it < 64; it++) {
                float s = 0.0f, kk = 0.0f;
#pragma unroll
                for (int i = 0; i < 32; i++) {
                    bool a = v[i] > tau;
                    s  += a ? v[i] : 0.0f;
                    kk += a ? 1.0f : 0.0f;
                }
                s  = warp_sum(s);
                kk = warp_sum(kk);
                float nt = (s - 1.0f) / kk;
                if (nt == tau) break;
                tau = nt;
            }
        }

        // ---- write p = relu(z - tau), coalesced float4 streaming stores ----
#pragma unroll
        for (int j = 0; j < 8; j++) {
            float4 t;
            t.x = fmaxf(v[4 * j + 0] - tau, 0.0f);
            t.y = fmaxf(v[4 * j + 1] - tau, 0.0f);
            t.z = fmaxf(v[4 * j + 2] - tau, 0.0f);
            t.w = fmaxf(v[4 * j + 3] - tau, 0.0f);
            __stcs(reinterpret_cast<float4*>(pr + j * 128), t);
        }
    }
}

extern "C" void kernel_launch(void* const* d_in, const int* in_sizes, int n_in,
                              void* d_out, int out_size) {
    const float* z = (const float*)d_in[0];
    float* p = (float*)d_out;
    const int rows = in_sizes[0] / D;                  // 32768
    int grid = GRID_PERSIST;                           // 1332: one full wave
    const int max_needed = (rows + WPB - 1) / WPB;
    if (grid > max_needed) grid = max_needed;
    sparsemax_kernel<<<grid, TPB>>>(z, p, rows);
}

// round 16
// speedup vs baseline: 1.1606x; 1.1606x over previous
#include <cuda_runtime.h>
#include <cstdint>
#include <math_constants.h>

// Sparsemax along last dim (d = 1024), one warp per row, row in registers.
// Michelot fixed-point warm-started at tau0 = max(z)-1 (valid: tau* >= max-1).
// CHANGE vs champion (R13): the FIRST Michelot step runs on the full register
// file with pure ILP (no serial chain), producing tau1; actives are then
// binned at tau1 (|actives| ~= k*, so overflow is ultra-rare and the redux
// loop starts one step from the fixed point). Iterations use
// single-instruction integer redux.sync on 2^21 fixed-point sums.
// __launch_bounds__(128, 9) pins the 9-blocks/SM target (<=56 regs).
// No smem, no block barriers.

constexpr int D   = 1024;
constexpr int WPB = 4;               // warps (rows) per block
constexpr int TPB = WPB * 32;        // 128 threads

#define FPSCALE     2097152.0f        // 2^21
#define FPSCALE_INV 4.76837158203125e-7f

// Order-preserving float<->int mapping (valid for non-NaN inputs).
__device__ __forceinline__ int f2i_mono(float f) {
    int i = __float_as_int(f);
    return i >= 0 ? i : i ^ 0x7fffffff;
}
__device__ __forceinline__ float i2f_mono(int i) {
    return __int_as_float(i >= 0 ? i : i ^ 0x7fffffff);
}

__device__ __forceinline__ float warp_sum(float x) {
#pragma unroll
    for (int o = 16; o > 0; o >>= 1)
        x += __shfl_xor_sync(0xffffffffu, x, o);
    return x;
}

__global__ void __launch_bounds__(TPB, 9)
sparsemax_kernel(const float* __restrict__ z, float* __restrict__ p, int rows) {
    const int wl   = threadIdx.x >> 5;
    const int lane = threadIdx.x & 31;
    const int row  = blockIdx.x * WPB + wl;
    if (row >= rows) return;

    const float* zr = z + (size_t)row * D + lane * 4;
    float*       pr = p + (size_t)row * D + lane * 4;

    // ---- load row: 8 x float4 per lane, coalesced, streaming ----
    float v[32];
#pragma unroll
    for (int j = 0; j < 8; j++) {
        float4 t = __ldcs(reinterpret_cast<const float4*>(zr + j * 128));
        v[4 * j + 0] = t.x;
        v[4 * j + 1] = t.y;
        v[4 * j + 2] = t.z;
        v[4 * j + 3] = t.w;
    }

    // ---- row max: register tree (ILP) + single-instruction int redux ----
    float m = v[0];
#pragma unroll
    for (int i = 1; i < 32; i++) m = fmaxf(m, v[i]);
    m = i2f_mono(__reduce_max_sync(0xffffffffu, f2i_mono(m)));

    float tau = m - 1.0f;

    // ---- Michelot step 1 on the full register file (pure ILP) -> tau1 ----
    {
        float s = 0.0f, kk = 0.0f;
#pragma unroll
        for (int i = 0; i < 32; i++) {
            bool a = v[i] > tau;
            s  += a ? v[i] : 0.0f;
            kk += a ? 1.0f : 0.0f;
        }
        int S = __reduce_add_sync(0xffffffffu, __float2int_rn(s * FPSCALE));
        int K = __reduce_add_sync(0xffffffffu, (int)kk);   // K >= 1 always
        tau = ((float)S * FPSCALE_INV - 1.0f) / (float)K;
    }

    // ---- bin actives at tau1 (|actives| ~= k*): 2 chains, 3+3 slots ----
    float x0 = -CUDART_INF_F, x1 = -CUDART_INF_F, x2 = -CUDART_INF_F;
    float x3 = -CUDART_INF_F, x4 = -CUDART_INF_F, x5 = -CUDART_INF_F;
    int lc0 = 0, lc1 = 0;
#pragma unroll
    for (int i = 0; i < 16; i++) {
        if (v[i] > tau) {
            if (lc0 == 0)      x0 = v[i];
            else if (lc0 == 1) x1 = v[i];
            else if (lc0 == 2) x2 = v[i];
            lc0++;
        }
    }
#pragma unroll
    for (int i = 16; i < 32; i++) {
        if (v[i] > tau) {
            if (lc1 == 0)      x3 = v[i];
            else if (lc1 == 1) x4 = v[i];
            else if (lc1 == 2) x5 = v[i];
            lc1++;
        }
    }
    const bool overflow =
        __ballot_sync(0xffffffffu, (lc0 > 3) || (lc1 > 3)) != 0u;

    // ---- remaining Michelot fixed-point iterations ----
    if (!overflow) {
        // common case: all actives in x0..x5 across the warp
#pragma unroll 1
        for (int it = 0; it < 40; it++) {
            bool a0 = x0 > tau, a1 = x1 > tau, a2 = x2 > tau;
            bool a3 = x3 > tau, a4 = x4 > tau, a5 = x5 > tau;
            float ls = ((a0 ? x0 : 0.0f) + (a1 ? x1 : 0.0f))
                     + ((a2 ? x2 : 0.0f) + (a3 ? x3 : 0.0f))
                     + ((a4 ? x4 : 0.0f) + (a5 ? x5 : 0.0f));
            int lk = (int)a0 + (int)a1 + (int)a2
                   + (int)a3 + (int)a4 + (int)a5;
            int S = __reduce_add_sync(0xffffffffu, __float2int_rn(ls * FPSCALE));
            int K = __reduce_add_sync(0xffffffffu, lk);      // K >= 1 always
            float nt = ((float)S * FPSCALE_INV - 1.0f) / (float)K;
            if (nt == tau) break;   // fixed point = exact sparsemax threshold
            tau = nt;
        }
    } else {
        // ultra-rare fallback: full register row, float shuffle reductions
#pragma unroll 1
        for (int it = 0; it < 64; it++) {
            float s = 0.0f, kk = 0.0f;
#pragma unroll
            for (int i = 0; i < 32; i++) {
                bool a = v[i] > tau;
                s  += a ? v[i] : 0.0f;
                kk += a ? 1.0f : 0.0f;
            }
            s  = warp_sum(s);
            kk = warp_sum(kk);
            float nt = (s - 1.0f) / kk;
            if (nt == tau) break;
            tau = nt;
        }
    }

    // ---- write p = relu(z - tau), coalesced float4 streaming stores ----
#pragma unroll
    for (int j = 0; j < 8; j++) {
        float4 t;
        t.x = fmaxf(v[4 * j + 0] - tau, 0.0f);
        t.y = fmaxf(v[4 * j + 1] - tau, 0.0f);
        t.z = fmaxf(v[4 * j + 2] - tau, 0.0f);
        t.w = fmaxf(v[4 * j + 3] - tau, 0.0f);
        __stcs(reinterpret_cast<float4*>(pr + j * 128), t);
    }
}

extern "C" void kernel_launch(void* const* d_in, const int* in_sizes, int n_in,
                              void* d_out, int out_size) {
    const float* z = (const float*)d_in[0];
    float* p = (float*)d_out;
    const int rows = in_sizes[0] / D;                  // 32768
    const int grid = (rows + WPB - 1) / WPB;           // 8192
    sparsemax_kernel<<<grid, TPB>>>(z, p, rows);
}

// round 17
// speedup vs baseline: 1.1771x; 1.0142x over previous
#include <cuda_runtime.h>
#include <cstdint>
#include <math_constants.h>

// Sparsemax along last dim (d = 1024), one warp per row, row in registers.
// Compute identical to champion (R13): Michelot fixed-point from
// tau0 = max(z)-1 (valid: tau* >= max-1), actives binned into 3+3 regs/lane
// via two independent 16-deep chains, iterations via single-instruction
// integer redux.sync on 2^21 fixed-point sums. Rare overflow ->
// full-register float-shuffle fallback. No smem, no block barriers.
// 128-thread blocks (9 blocks/SM at 55 regs).
//
// CHANGE vs R13: 256-bit (v8.b32) loads and stores — 4 LDG.256 + 4 STG.256
// per lane instead of 8+8 128-bit ops, halving memory issue slots and
// addressing arithmetic. evict_first qualifier (required for v8 on sm_103a)
// matches the single-use streaming pattern.

constexpr int D   = 1024;
constexpr int WPB = 4;               // warps (rows) per block
constexpr int TPB = WPB * 32;        // 128 threads

#define FPSCALE     2097152.0f        // 2^21
#define FPSCALE_INV 4.76837158203125e-7f

// Order-preserving float<->int mapping (valid for non-NaN inputs).
__device__ __forceinline__ int f2i_mono(float f) {
    int i = __float_as_int(f);
    return i >= 0 ? i : i ^ 0x7fffffff;
}
__device__ __forceinline__ float i2f_mono(int i) {
    return __int_as_float(i >= 0 ? i : i ^ 0x7fffffff);
}

__device__ __forceinline__ float warp_sum(float x) {
#pragma unroll
    for (int o = 16; o > 0; o >>= 1)
        x += __shfl_xor_sync(0xffffffffu, x, o);
    return x;
}

// 256-bit streaming load (evict_first is the qualifier ptxas requires for v8).
__device__ __forceinline__ void ldg256(const float* p, float* d) {
    asm volatile(
        "ld.global.nc.L2::evict_first.v8.b32 {%0,%1,%2,%3,%4,%5,%6,%7}, [%8];"
        : "=f"(d[0]), "=f"(d[1]), "=f"(d[2]), "=f"(d[3]),
          "=f"(d[4]), "=f"(d[5]), "=f"(d[6]), "=f"(d[7])
        : "l"(p));
}
// 256-bit streaming store.
__device__ __forceinline__ void stg256(float* p, const float* s) {
    asm volatile(
        "st.global.L2::evict_first.v8.b32 [%0], {%1,%2,%3,%4,%5,%6,%7,%8};"
        :: "l"(p),
           "f"(s[0]), "f"(s[1]), "f"(s[2]), "f"(s[3]),
           "f"(s[4]), "f"(s[5]), "f"(s[6]), "f"(s[7])
        : "memory");
}

__global__ void __launch_bounds__(TPB)
sparsemax_kernel(const float* __restrict__ z, float* __restrict__ p, int rows) {
    const int wl   = threadIdx.x >> 5;
    const int lane = threadIdx.x & 31;
    const int row  = blockIdx.x * WPB + wl;
    if (row >= rows) return;

    const float* zr = z + (size_t)row * D + lane * 8;
    float*       pr = p + (size_t)row * D + lane * 8;

    // ---- load row: 4 x 32B per lane, coalesced (1KB warp transactions) ----
    float v[32];
#pragma unroll
    for (int j = 0; j < 4; j++)
        ldg256(zr + j * 256, &v[8 * j]);

    // ---- row max: register tree (ILP) + single-instruction int redux ----
    float m = v[0];
#pragma unroll
    for (int i = 1; i < 32; i++) m = fmaxf(m, v[i]);
    m = i2f_mono(__reduce_max_sync(0xffffffffu, f2i_mono(m)));

    float tau = m - 1.0f;

    // ---- bin actives {z > tau0}: two independent 16-deep chains, 3+3 slots ----
    float x0 = -CUDART_INF_F, x1 = -CUDART_INF_F, x2 = -CUDART_INF_F;
    float x3 = -CUDART_INF_F, x4 = -CUDART_INF_F, x5 = -CUDART_INF_F;
    int lc0 = 0, lc1 = 0;
#pragma unroll
    for (int i = 0; i < 16; i++) {
        if (v[i] > tau) {
            if (lc0 == 0)      x0 = v[i];
            else if (lc0 == 1) x1 = v[i];
            else if (lc0 == 2) x2 = v[i];
            lc0++;
        }
    }
#pragma unroll
    for (int i = 16; i < 32; i++) {
        if (v[i] > tau) {
            if (lc1 == 0)      x3 = v[i];
            else if (lc1 == 1) x4 = v[i];
            else if (lc1 == 2) x5 = v[i];
            lc1++;
        }
    }
    const bool overflow =
        __ballot_sync(0xffffffffu, (lc0 > 3) || (lc1 > 3)) != 0u;

    // ---- Michelot fixed-point iterations ----
    if (!overflow) {
        // common case: all actives in x0..x5 across the warp.
        // Sums via integer redux.sync on 2^21 fixed point (single instr).
#pragma unroll 1
        for (int it = 0; it < 40; it++) {
            bool a0 = x0 > tau, a1 = x1 > tau, a2 = x2 > tau;
            bool a3 = x3 > tau, a4 = x4 > tau, a5 = x5 > tau;
            float ls = ((a0 ? x0 : 0.0f) + (a1 ? x1 : 0.0f))
                     + ((a2 ? x2 : 0.0f) + (a3 ? x3 : 0.0f))
                     + ((a4 ? x4 : 0.0f) + (a5 ? x5 : 0.0f));
            int lk = (int)a0 + (int)a1 + (int)a2
                   + (int)a3 + (int)a4 + (int)a5;
            int S = __reduce_add_sync(0xffffffffu, __float2int_rn(ls * FPSCALE));
            int K = __reduce_add_sync(0xffffffffu, lk);      // K >= 1 always
            float nt = ((float)S * FPSCALE_INV - 1.0f) / (float)K;
            if (nt == tau) break;   // set stable -> fixed point reached
            tau = nt;
        }
    } else {
        // rare fallback: full register row, pure float shuffle reductions
#pragma unroll 1
        for (int it = 0; it < 64; it++) {
            float s = 0.0f, kk = 0.0f;
#pragma unroll
            for (int i = 0; i < 32; i++) {
                bool a = v[i] > tau;
                s  += a ? v[i] : 0.0f;
                kk += a ? 1.0f : 0.0f;
            }
            s  = warp_sum(s);
            kk = warp_sum(kk);
            float nt = (s - 1.0f) / kk;
            if (nt == tau) break;
            tau = nt;
        }
    }

    // ---- write p = relu(z - tau): 4 x 32B streaming stores per lane ----
#pragma unroll
    for (int j = 0; j < 4; j++) {
        float o[8];
#pragma unroll
        for (int q = 0; q < 8; q++)
            o[q] = fmaxf(v[8 * j + q] - tau, 0.0f);
        stg256(pr + j * 256, o);
    }
}

extern "C" void kernel_launch(void* const* d_in, const int* in_sizes, int n_in,
                              void* d_out, int out_size) {
    const float* z = (const float*)d_in[0];
    float* p = (float*)d_out;
    const int rows = in_sizes[0] / D;                  // 32768
    const int grid = (rows + WPB - 1) / WPB;           // 8192
    sparsemax_kernel<<<grid, TPB>>>(z, p, rows);
}